// round 16
// baseline (speedup 1.0000x reference)
#include <cuda_runtime.h>
#include <math.h>
#include <stdint.h>

#define NUx 200000
#define NSx 50000
#define NEx 1000000
#define NMx 100000
#define Hx  128

// ---------------- scratch (device globals; no allocation allowed) ----------------
__device__ float g_aggU [(size_t)NUx * Hx];
__device__ float g_aggS [(size_t)NSx * Hx];
__device__ float g_aggU2[(size_t)NUx * Hx];
__device__ float g_aggS2[(size_t)NSx * Hx];
__device__ float g_u1  [(size_t)NUx * Hx];
__device__ float g_s1  [(size_t)NSx * Hx];
__device__ float g_dotU[NUx];
__device__ float g_dotS[NSx];
__device__ int   g_cntU[NUx];
__device__ int   g_cntS[NSx];
__device__ int   g_offU[NUx];
__device__ int   g_offS[NSx];
__device__ int   g_curU[NUx];
__device__ int   g_curS[NSx];
__device__ int   g_csrU[NEx];
__device__ int   g_csrS[NEx];
__device__ int   g_lstU[NUx];
__device__ int   g_lstS[NSx];
__device__ int   g_alloc[4];      // [0]=csrU base, [1]=csrS base, [2]=nU, [3]=nS
__device__ int   g_flagU[NUx];
__device__ int   g_flagS[NSx];
__device__ uint32_t g_Bimg[4 * 32768];

__device__ __forceinline__ uint32_t f2tf32(float x) {
    uint32_t r;
    asm("cvt.rna.tf32.f32 %0, %1;" : "=r"(r) : "f"(x));
    return r;
}

// ---------------- prep: zero counts/flags/alloc ----------------
__global__ void prep_zero(int* cntU, int* cntS, int* fu, int* fs, int* alloc4) {
    int i = blockIdx.x * blockDim.x + threadIdx.x;
    if (i < NUx) { cntU[i] = 0; fu[i] = 0; }
    if (i < NSx) { cntS[i] = 0; fs[i] = 0; }
    if (i < 4)   alloc4[i] = 0;
}

// ---------------- flag + dedupe-compact mask members ----------------
__global__ void flag_compact(const int* __restrict__ mu, const int* __restrict__ ms,
                             int* __restrict__ fu, int* __restrict__ fs,
                             int* __restrict__ lstU, int* __restrict__ lstS,
                             int* __restrict__ alloc4) {
    int m = blockIdx.x * blockDim.x + threadIdx.x;
    if (m >= NMx) return;
    int u = mu[m];
    if (atomicExch(&fu[u], 1) == 0) { int p = atomicAdd(&alloc4[2], 1); lstU[p] = u; }
    int s = ms[m];
    if (atomicExch(&fs[s], 1) == 0) { int p = atomicAdd(&alloc4[3], 1); lstS[p] = s; }
}

// ---------------- one-sided degree count ----------------
__global__ void count_one(const int* __restrict__ dst, int* __restrict__ cnt) {
    int e = blockIdx.x * blockDim.x + threadIdx.x;
    if (e >= NEx) return;
    atomicAdd(&cnt[dst[e]], 1);
}

// ---------------- CSR segment allocation (block scan + atomic bump) ----------------
__global__ void __launch_bounds__(256)
alloc_kernel(const int* __restrict__ cnt, int* __restrict__ off, int* __restrict__ cur,
             int N, int* __restrict__ alloc4, int cidx) {
    __shared__ int sc[256];
    __shared__ int base;
    int i = blockIdx.x * 256 + threadIdx.x;
    int v = (i < N) ? cnt[i] : 0;
    sc[threadIdx.x] = v;
    __syncthreads();
#pragma unroll
    for (int d = 1; d < 256; d <<= 1) {
        int t = (threadIdx.x >= d) ? sc[threadIdx.x - d] : 0;
        __syncthreads();
        sc[threadIdx.x] += t;
        __syncthreads();
    }
    if (threadIdx.x == 255) base = atomicAdd(&alloc4[cidx], sc[255]);
    __syncthreads();
    if (i < N) {
        int excl = sc[threadIdx.x] - v + base;
        off[i] = excl;
        cur[i] = excl;
    }
}

// ---------------- one-sided CSR fill ----------------
__global__ void fill_one(const int* __restrict__ src, const int* __restrict__ dst,
                         int* __restrict__ cur, int* __restrict__ csr) {
    int e = blockIdx.x * blockDim.x + threadIdx.x;
    if (e >= NEx) return;
    int d = dst[e];
    int p = atomicAdd(&cur[d], 1);
    csr[p] = src[e];
}

// ---------------- CSR gather ----------------
template<int LG, bool FLAG, bool XU>
__global__ void __launch_bounds__(256)
gather_rows(const float* __restrict__ feat, const int* __restrict__ csr,
            const int* __restrict__ off, const int* __restrict__ cnt,
            float* __restrict__ agg, int Nrows, const int* __restrict__ flag,
            const int* __restrict__ x1, const float* __restrict__ aemb,
            const float* __restrict__ gemb)
{
    constexpr int F4 = 1 << LG;
    long long g = (long long)blockIdx.x * blockDim.x + threadIdx.x;
    int r = (int)(g >> LG);
    if (r >= Nrows) return;
    if (FLAG && !flag[r]) return;
    const int c = threadIdx.x & (F4 - 1);
    const int o = off[r], n = cnt[r];

    auto ld = [&](int nb) -> float4 {
        if (XU) {
            if (c < 8)  return ((const float4*)aemb)[((const int2*)x1)[nb].x * 8 + c];
            if (c < 16) return ((const float4*)gemb)[((const int2*)x1)[nb].y * 8 + (c - 8)];
            return ((const float4*)feat)[(size_t)nb * 16 + (c - 16)];
        }
        return ((const float4*)feat)[(size_t)nb * F4 + c];
    };

    float4 acc = make_float4(0.f, 0.f, 0.f, 0.f);
    int i = 0;
    for (; i + 4 <= n; i += 4) {
        int nb0 = csr[o + i],     nb1 = csr[o + i + 1];
        int nb2 = csr[o + i + 2], nb3 = csr[o + i + 3];
        float4 a = ld(nb0);
        float4 b = ld(nb1);
        float4 e = ld(nb2);
        float4 f = ld(nb3);
        acc.x += (a.x + b.x) + (e.x + f.x);
        acc.y += (a.y + b.y) + (e.y + f.y);
        acc.z += (a.z + b.z) + (e.z + f.z);
        acc.w += (a.w + b.w) + (e.w + f.w);
    }
    for (; i < n; i++) {
        float4 a = ld(csr[o + i]);
        acc.x += a.x; acc.y += a.y; acc.z += a.z; acc.w += a.w;
    }
    ((float4*)agg)[(size_t)r * F4 + c] = acc;
}

// ---------------- build tf32 weight image in m16n8k8 B-fragment layout ----------------
__global__ void build_B_kernel(const float* __restrict__ Wl, const float* __restrict__ Wr,
                               int FA, int K, uint32_t* __restrict__ img) {
    int tid = blockIdx.x * blockDim.x + threadIdx.x;
    if (tid >= K * 128) return;
    int k = tid >> 7, n = tid & 127;
    float v = (k < FA) ? Wl[k * 128 + n] : Wr[(k - FA) * 128 + n];
    int ntile = n >> 3;
    int lane  = ((n & 7) << 2) | (k & 3);
    int reg   = (k >> 2) & 1;
    int kstep = k >> 3;
    img[((ntile * (K >> 3) + kstep) * 32 + lane) * 2 + reg] = f2tf32(v);
}

// ================= tf32 mma.sync GEMM core, 64-row M-tile =========
// Warp grid 1M x 8N: each warp owns all 64 rows x 16 cols -> half the B traffic.
template<int FA, int FB, bool DOT, bool GATHER, bool XUF, int MAXB>
__global__ void __launch_bounds__(256, MAXB)
gemm_mma(const float* __restrict__ agg, const int* __restrict__ cnt,
         const float* __restrict__ xr, const uint32_t* __restrict__ Bfrag,
         const float* __restrict__ bias, const float* __restrict__ lw,
         float* __restrict__ out, int Nrows, const int* __restrict__ lst,
         const int* __restrict__ ndev,
         const int* __restrict__ x1, const float* __restrict__ aemb,
         const float* __restrict__ gemb)
{
    constexpr int K   = FA + FB;
    constexpr int KS  = K / 8;
    constexpr int LDA = K + 4;
    constexpr int J   = K / 16;

    const int tile0 = blockIdx.x * 64;
    int nr = Nrows;
    if (DOT && ndev) nr = *ndev;
    if (tile0 >= nr) return;

    extern __shared__ uint32_t sA[];
    float* part = (float*)(sA + 64 * LDA);
    const int tid  = threadIdx.x;
    const int wid  = tid >> 5;
    const int lane = tid & 31;

    {
        const int row = tid >> 2;
        const int q   = tid & 3;
        int idx = tile0 + row; if (idx >= nr) idx = nr - 1;
        int grow = GATHER ? lst[idx] : idx;
        int c = cnt[grow];
        const float inv = 1.f / (float)(c > 1 ? c : 1);
        const float4* pa = (const float4*)(agg + (size_t)grow * FA);
        const float4* px = (const float4*)(xr  + (size_t)grow * FB);
        int ax = 0, gx = 0;
        if (XUF) { int2 xx = ((const int2*)x1)[grow]; ax = xx.x; gx = xx.y; }
#pragma unroll
        for (int j = 0; j < J; j++) {
            int k4 = q * J + j;
            int kf = k4 * 4;
            float4 v; float sc;
            if (kf < FA) { v = pa[k4]; sc = inv; }
            else if (XUF) {
                int cc = k4 - FA / 4;
                if (cc < 8)       v = ((const float4*)aemb)[ax * 8 + cc];
                else if (cc < 16) v = ((const float4*)gemb)[gx * 8 + (cc - 8)];
                else              v = ((const float4*)xr)[(size_t)grow * 16 + (cc - 16)];
                sc = 1.f;
            } else { v = px[k4 - FA / 4]; sc = 1.f; }
            uint4 t;
            t.x = f2tf32(v.x * sc); t.y = f2tf32(v.y * sc);
            t.z = f2tf32(v.z * sc); t.w = f2tf32(v.w * sc);
            *(uint4*)(sA + row * LDA + kf) = t;
        }
        if (DOT && tid < 64) part[tid] = 0.f;
    }
    __syncthreads();

    const int wn = wid;          // 8 column groups of 16
    const int lr = lane >> 2;
    const int lc = lane & 3;

    float acc[4][2][4];
#pragma unroll
    for (int t = 0; t < 4; t++)
#pragma unroll
        for (int nt = 0; nt < 2; nt++)
#pragma unroll
            for (int q = 0; q < 4; q++) acc[t][nt][q] = 0.f;

    const uint32_t* Ab = sA + lr * LDA + lc;
    const uint2* Bp = (const uint2*)Bfrag + (size_t)(wn * 2) * KS * 32 + lane;

    uint2 bc[2], bn[2];
#pragma unroll
    for (int nt = 0; nt < 2; nt++) bc[nt] = Bp[nt * KS * 32];

#pragma unroll
    for (int ks = 0; ks < KS; ks++) {
        if (ks + 1 < KS) {
#pragma unroll
            for (int nt = 0; nt < 2; nt++) bn[nt] = Bp[nt * KS * 32 + (ks + 1) * 32];
        }
        uint32_t a[4][4];
#pragma unroll
        for (int t = 0; t < 4; t++) {
            const uint32_t* p = Ab + t * 16 * LDA + ks * 8;
            a[t][0] = p[0];
            a[t][1] = p[8 * LDA];
            a[t][2] = p[4];
            a[t][3] = p[8 * LDA + 4];
        }
#pragma unroll
        for (int t = 0; t < 4; t++)
#pragma unroll
            for (int nt = 0; nt < 2; nt++) {
                asm volatile(
                    "mma.sync.aligned.m16n8k8.row.col.f32.tf32.tf32.f32 "
                    "{%0,%1,%2,%3}, {%4,%5,%6,%7}, {%8,%9}, {%0,%1,%2,%3};"
                    : "+f"(acc[t][nt][0]), "+f"(acc[t][nt][1]),
                      "+f"(acc[t][nt][2]), "+f"(acc[t][nt][3])
                    : "r"(a[t][0]), "r"(a[t][1]), "r"(a[t][2]), "r"(a[t][3]),
                      "r"(bc[nt].x), "r"(bc[nt].y));
            }
#pragma unroll
        for (int nt = 0; nt < 2; nt++) bc[nt] = bn[nt];
    }

    if (!DOT) {
#pragma unroll
        for (int nt = 0; nt < 2; nt++) {
            const int col = wn * 16 + nt * 8 + lc * 2;
            const float2 bv = *(const float2*)(bias + col);
#pragma unroll
            for (int t = 0; t < 4; t++) {
                int r0 = tile0 + t * 16 + lr;
                if (r0 < nr) {
                    float2 o;
                    o.x = fmaxf(acc[t][nt][0] + bv.x, 0.f);
                    o.y = fmaxf(acc[t][nt][1] + bv.y, 0.f);
                    *(float2*)(out + (size_t)r0 * 128 + col) = o;
                }
                int r1 = r0 + 8;
                if (r1 < nr) {
                    float2 o;
                    o.x = fmaxf(acc[t][nt][2] + bv.x, 0.f);
                    o.y = fmaxf(acc[t][nt][3] + bv.y, 0.f);
                    *(float2*)(out + (size_t)r1 * 128 + col) = o;
                }
            }
        }
    } else {
        float p[4][2];
#pragma unroll
        for (int t = 0; t < 4; t++) { p[t][0] = 0.f; p[t][1] = 0.f; }
#pragma unroll
        for (int nt = 0; nt < 2; nt++) {
            const int col = wn * 16 + nt * 8 + lc * 2;
            const float2 bv = *(const float2*)(bias + col);
            const float2 wv = *(const float2*)(lw + col);
#pragma unroll
            for (int t = 0; t < 4; t++) {
                p[t][0] += fmaxf(acc[t][nt][0] + bv.x, 0.f) * wv.x
                         + fmaxf(acc[t][nt][1] + bv.y, 0.f) * wv.y;
                p[t][1] += fmaxf(acc[t][nt][2] + bv.x, 0.f) * wv.x
                         + fmaxf(acc[t][nt][3] + bv.y, 0.f) * wv.y;
            }
        }
#pragma unroll
        for (int t = 0; t < 4; t++)
#pragma unroll
            for (int h = 0; h < 2; h++) {
                p[t][h] += __shfl_xor_sync(0xffffffffu, p[t][h], 1);
                p[t][h] += __shfl_xor_sync(0xffffffffu, p[t][h], 2);
            }
        if (lc == 0) {
#pragma unroll
            for (int t = 0; t < 4; t++) {
                atomicAdd(&part[t * 16 + lr],     p[t][0]);
                atomicAdd(&part[t * 16 + lr + 8], p[t][1]);
            }
        }
        __syncthreads();
        if (tid < 64) {
            int idx = tile0 + tid;
            if (idx < nr) out[GATHER ? lst[idx] : idx] = part[tid];
        }
    }
}

// ---------------- head: gather both dots, sigmoid ----------------
__global__ void final_kernel(const int* __restrict__ mu, const int* __restrict__ ms,
                             const float* __restrict__ dotU,
                             const float* __restrict__ dotS,
                             const float* __restrict__ lb,
                             float* __restrict__ out) {
    int m = blockIdx.x * blockDim.x + threadIdx.x;
    if (m >= NMx) return;
    float s = dotU[mu[m]] + dotS[ms[m]] + lb[0];
    out[m] = 1.f / (1.f + expf(-s));
}

// ---------------- launcher ----------------
extern "C" void kernel_launch(void* const* d_in, const int* in_sizes, int n_in,
                              void* d_out, int out_size) {
    (void)in_sizes; (void)n_in; (void)out_size;
    const float* x_user_feat   = (const float*)d_in[0];
    const float* x_seller_feat = (const float*)d_in[1];
    const int*   x1            = (const int*)  d_in[2];
    const int*   src_user      = (const int*)  d_in[3];
    const int*   dst_seller    = (const int*)  d_in[4];
    const int*   src_seller    = (const int*)  d_in[5];
    const int*   dst_user      = (const int*)  d_in[6];
    const int*   mask_user     = (const int*)  d_in[7];
    const int*   mask_seller   = (const int*)  d_in[8];
    const float* age_emb       = (const float*)d_in[9];
    const float* gen_emb       = (const float*)d_in[10];
    const float* W1ul = (const float*)d_in[11];
    const float* W1ur = (const float*)d_in[12];
    const float* b1u  = (const float*)d_in[13];
    const float* W1sl = (const float*)d_in[14];
    const float* W1sr = (const float*)d_in[15];
    const float* b1s  = (const float*)d_in[16];
    const float* W2ul = (const float*)d_in[17];
    const float* W2ur = (const float*)d_in[18];
    const float* b2u  = (const float*)d_in[19];
    const float* W2sl = (const float*)d_in[20];
    const float* W2sr = (const float*)d_in[21];
    const float* b2s  = (const float*)d_in[22];
    const float* lin_w = (const float*)d_in[23];
    const float* lin_b = (const float*)d_in[24];
    float* out = (float*)d_out;

    float *aggU, *aggS, *aggU2, *aggS2, *u1, *s1, *dotU, *dotS;
    int *cntU, *cntS, *offU, *offS, *curU, *curS, *csrU, *csrS, *alloc4;
    int *flagU, *flagS, *lstU, *lstS;
    uint32_t* Bimg;
    cudaGetSymbolAddress((void**)&aggU,  g_aggU);
    cudaGetSymbolAddress((void**)&aggS,  g_aggS);
    cudaGetSymbolAddress((void**)&aggU2, g_aggU2);
    cudaGetSymbolAddress((void**)&aggS2, g_aggS2);
    cudaGetSymbolAddress((void**)&u1,    g_u1);
    cudaGetSymbolAddress((void**)&s1,    g_s1);
    cudaGetSymbolAddress((void**)&dotU,  g_dotU);
    cudaGetSymbolAddress((void**)&dotS,  g_dotS);
    cudaGetSymbolAddress((void**)&cntU,  g_cntU);
    cudaGetSymbolAddress((void**)&cntS,  g_cntS);
    cudaGetSymbolAddress((void**)&offU,  g_offU);
    cudaGetSymbolAddress((void**)&offS,  g_offS);
    cudaGetSymbolAddress((void**)&curU,  g_curU);
    cudaGetSymbolAddress((void**)&curS,  g_curS);
    cudaGetSymbolAddress((void**)&csrU,  g_csrU);
    cudaGetSymbolAddress((void**)&csrS,  g_csrS);
    cudaGetSymbolAddress((void**)&lstU,  g_lstU);
    cudaGetSymbolAddress((void**)&lstS,  g_lstS);
    cudaGetSymbolAddress((void**)&alloc4, g_alloc);
    cudaGetSymbolAddress((void**)&flagU, g_flagU);
    cudaGetSymbolAddress((void**)&flagS, g_flagS);
    cudaGetSymbolAddress((void**)&Bimg,  g_Bimg);

    const int SM192 = 64 * (192 + 4) * 4;          // 50176
    const int SM256 = 64 * (256 + 4) * 4 + 256;    // 66816
    cudaFuncSetAttribute((const void*)gemm_mma<64,128,false,false,true,3>,
                         cudaFuncAttributeMaxDynamicSharedMemorySize, SM192);
    cudaFuncSetAttribute((const void*)gemm_mma<128,64,false,false,false,3>,
                         cudaFuncAttributeMaxDynamicSharedMemorySize, SM192);
    cudaFuncSetAttribute((const void*)gemm_mma<128,128,true,true,false,2>,
                         cudaFuncAttributeMaxDynamicSharedMemorySize, SM256);

    static cudaStream_t s2 = nullptr;
    static cudaEvent_t evF, evPrep, evCSRS, evCSRU, evU1, evS1, evG2U;
    if (!s2) {
        cudaStreamCreateWithFlags(&s2, cudaStreamNonBlocking);
        cudaEventCreateWithFlags(&evF,    cudaEventDisableTiming);
        cudaEventCreateWithFlags(&evPrep, cudaEventDisableTiming);
        cudaEventCreateWithFlags(&evCSRS, cudaEventDisableTiming);
        cudaEventCreateWithFlags(&evCSRU, cudaEventDisableTiming);
        cudaEventCreateWithFlags(&evU1,   cudaEventDisableTiming);
        cudaEventCreateWithFlags(&evS1,   cudaEventDisableTiming);
        cudaEventCreateWithFlags(&evG2U,  cudaEventDisableTiming);
    }
    cudaStream_t s0 = 0;
    const int T = 256;

    // ---- fork ----
    cudaEventRecord(evF, s0);
    cudaStreamWaitEvent(s2, evF, 0);

    // ---- s0: shared prep (zeros, flags + compact lists) ----
    prep_zero<<<(NUx + T - 1) / T, T, 0, s0>>>(cntU, cntS, flagU, flagS, alloc4);
    flag_compact<<<(NMx + T - 1) / T, T, 0, s0>>>(mask_user, mask_seller,
                                                  flagU, flagS, lstU, lstS, alloc4);
    cudaEventRecord(evPrep, s0);

    // ---- s2: B images + seller-side CSR + seller L1 chain ----
    build_B_kernel<<<(192*128 + T - 1) / T, T, 0, s2>>>(W1sl, W1sr, 128, 192, Bimg + 1*32768);
    build_B_kernel<<<(256*128 + T - 1) / T, T, 0, s2>>>(W2ul, W2ur, 128, 256, Bimg + 2*32768);
    build_B_kernel<<<(256*128 + T - 1) / T, T, 0, s2>>>(W2sl, W2sr, 128, 256, Bimg + 3*32768);
    cudaStreamWaitEvent(s2, evPrep, 0);
    count_one<<<(NEx + T - 1) / T, T, 0, s2>>>(dst_seller, cntS);
    alloc_kernel<<<(NSx + 255) / 256, 256, 0, s2>>>(cntS, offS, curS, NSx, alloc4, 1);
    fill_one<<<(NEx + T - 1) / T, T, 0, s2>>>(src_user, dst_seller, curS, csrS);
    cudaEventRecord(evCSRS, s2);
    gather_rows<5,false,true><<<(NSx * 32 + T - 1) / T, T, 0, s2>>>(
        x_user_feat, csrS, offS, cntS, aggS, NSx, nullptr, x1, age_emb, gen_emb);
    gemm_mma<128,64,false,false,false,3><<<(NSx + 63) / 64, 256, SM192, s2>>>(
        aggS, cntS, x_seller_feat, Bimg + 1*32768, b1s, nullptr, s1, NSx,
        nullptr, nullptr, nullptr, nullptr, nullptr);
    cudaEventRecord(evS1, s2);

    // ---- s0: user-side CSR + user L1 chain + L2 seller branch ----
    build_B_kernel<<<(192*128 + T - 1) / T, T, 0, s0>>>(W1ul, W1ur, 64, 192, Bimg + 0*32768);
    count_one<<<(NEx + T - 1) / T, T, 0, s0>>>(dst_user, cntU);
    alloc_kernel<<<(NUx + 255) / 256, 256, 0, s0>>>(cntU, offU, curU, NUx, alloc4, 0);
    fill_one<<<(NEx + T - 1) / T, T, 0, s0>>>(src_seller, dst_user, curU, csrU);
    cudaEventRecord(evCSRU, s0);
    gather_rows<4,false,false><<<(NUx * 16 + T - 1) / T, T, 0, s0>>>(
        x_seller_feat, csrU, offU, cntU, aggU, NUx, nullptr, nullptr, nullptr, nullptr);
    gemm_mma<64,128,false,false,true,3><<<(NUx + 63) / 64, 256, SM192, s0>>>(
        aggU, cntU, x_user_feat, Bimg + 0*32768, b1u, nullptr, u1, NUx,
        nullptr, nullptr, x1, age_emb, gen_emb);
    cudaEventRecord(evU1, s0);
    cudaStreamWaitEvent(s0, evCSRS, 0);
    gather_rows<5,true,false><<<(NSx * 32 + T - 1) / T, T, 0, s0>>>(
        u1, csrS, offS, cntS, aggS2, NSx, flagS, nullptr, nullptr, nullptr);
    cudaStreamWaitEvent(s0, evS1, 0);
    // dotS over compact flagged-seller list
    gemm_mma<128,128,true,true,false,2><<<(NSx + 63) / 64, 256, SM256, s0>>>(
        aggS2, cntS, s1, Bimg + 3*32768, b2s, lin_w + 128, dotS, NSx,
        lstS, alloc4 + 3, nullptr, nullptr, nullptr);

    // ---- s2: L2 user branch over compact flagged-user list ----
    cudaStreamWaitEvent(s2, evCSRU, 0);
    gather_rows<5,true,false><<<(NUx * 32 + T - 1) / T, T, 0, s2>>>(
        s1, csrU, offU, cntU, aggU2, NUx, flagU, nullptr, nullptr, nullptr);
    cudaStreamWaitEvent(s2, evU1, 0);
    gemm_mma<128,128,true,true,false,2><<<(NMx + 63) / 64, 256, SM256, s2>>>(
        aggU2, cntU, u1, Bimg + 2*32768, b2u, lin_w, dotU, NMx,
        lstU, alloc4 + 2, nullptr, nullptr, nullptr);
    cudaEventRecord(evG2U, s2);

    // ---- join + head ----
    cudaStreamWaitEvent(s0, evG2U, 0);
    final_kernel<<<(NMx + T - 1) / T, T, 0, s0>>>(mask_user, mask_seller, dotU, dotS, lin_b, out);
}

// round 17
// speedup vs baseline: 1.0770x; 1.0770x over previous
#include <cuda_runtime.h>
#include <math.h>
#include <stdint.h>

#define NUx 200000
#define NSx 50000
#define NEx 1000000
#define NMx 100000
#define Hx  128

// ---------------- scratch (device globals; no allocation allowed) ----------------
__device__ float g_aggU [(size_t)NUx * Hx];
__device__ float g_aggS [(size_t)NSx * Hx];
__device__ float g_aggU2[(size_t)NUx * Hx];   // compact rows (list order)
__device__ float g_aggS2[(size_t)NSx * Hx];   // compact rows (list order)
__device__ float g_u1  [(size_t)NUx * Hx];
__device__ float g_s1  [(size_t)NSx * Hx];
__device__ float g_dotU[NUx];
__device__ float g_dotS[NSx];
__device__ int   g_cntU[NUx];
__device__ int   g_cntS[NSx];
__device__ int   g_offU[NUx];
__device__ int   g_offS[NSx];
__device__ int   g_curU[NUx];
__device__ int   g_curS[NSx];
__device__ int   g_csrU[NEx];
__device__ int   g_csrS[NEx];
__device__ int   g_lstU[NUx];
__device__ int   g_lstS[NSx];
__device__ int   g_alloc[4];      // [0]=csrU base, [1]=csrS base, [2]=nU, [3]=nS
__device__ int   g_flagU[NUx];
__device__ int   g_flagS[NSx];
__device__ uint32_t g_Bimg[4 * 32768];

__device__ __forceinline__ uint32_t f2tf32(float x) {
    uint32_t r;
    asm("cvt.rna.tf32.f32 %0, %1;" : "=r"(r) : "f"(x));
    return r;
}

// ---------------- prep: zero counts/flags/alloc ----------------
__global__ void prep_zero(int* cntU, int* cntS, int* fu, int* fs, int* alloc4) {
    int i = blockIdx.x * blockDim.x + threadIdx.x;
    if (i < NUx) { cntU[i] = 0; fu[i] = 0; }
    if (i < NSx) { cntS[i] = 0; fs[i] = 0; }
    if (i < 4)   alloc4[i] = 0;
}

// ---------------- flag + dedupe-compact mask members ----------------
__global__ void flag_compact(const int* __restrict__ mu, const int* __restrict__ ms,
                             int* __restrict__ fu, int* __restrict__ fs,
                             int* __restrict__ lstU, int* __restrict__ lstS,
                             int* __restrict__ alloc4) {
    int m = blockIdx.x * blockDim.x + threadIdx.x;
    if (m >= NMx) return;
    int u = mu[m];
    if (atomicExch(&fu[u], 1) == 0) { int p = atomicAdd(&alloc4[2], 1); lstU[p] = u; }
    int s = ms[m];
    if (atomicExch(&fs[s], 1) == 0) { int p = atomicAdd(&alloc4[3], 1); lstS[p] = s; }
}

// ---------------- one-sided degree count ----------------
__global__ void count_one(const int* __restrict__ dst, int* __restrict__ cnt) {
    int e = blockIdx.x * blockDim.x + threadIdx.x;
    if (e >= NEx) return;
    atomicAdd(&cnt[dst[e]], 1);
}

// ---------------- CSR segment allocation (block scan + atomic bump) ----------------
__global__ void __launch_bounds__(256)
alloc_kernel(const int* __restrict__ cnt, int* __restrict__ off, int* __restrict__ cur,
             int N, int* __restrict__ alloc4, int cidx) {
    __shared__ int sc[256];
    __shared__ int base;
    int i = blockIdx.x * 256 + threadIdx.x;
    int v = (i < N) ? cnt[i] : 0;
    sc[threadIdx.x] = v;
    __syncthreads();
#pragma unroll
    for (int d = 1; d < 256; d <<= 1) {
        int t = (threadIdx.x >= d) ? sc[threadIdx.x - d] : 0;
        __syncthreads();
        sc[threadIdx.x] += t;
        __syncthreads();
    }
    if (threadIdx.x == 255) base = atomicAdd(&alloc4[cidx], sc[255]);
    __syncthreads();
    if (i < N) {
        int excl = sc[threadIdx.x] - v + base;
        off[i] = excl;
        cur[i] = excl;
    }
}

// ---------------- one-sided CSR fill ----------------
__global__ void fill_one(const int* __restrict__ src, const int* __restrict__ dst,
                         int* __restrict__ cur, int* __restrict__ csr) {
    int e = blockIdx.x * blockDim.x + threadIdx.x;
    if (e >= NEx) return;
    int d = dst[e];
    int p = atomicAdd(&cur[d], 1);
    csr[p] = src[e];
}

// ---------------- CSR gather ----------------
// GIDX: rows indexed by compact list lst[0..*ndev); agg written densely at r.
template<int LG, bool GIDX, bool XU>
__global__ void __launch_bounds__(256)
gather_rows(const float* __restrict__ feat, const int* __restrict__ csr,
            const int* __restrict__ off, const int* __restrict__ cnt,
            float* __restrict__ agg, int Nrows,
            const int* __restrict__ lst, const int* __restrict__ ndev,
            const int* __restrict__ x1, const float* __restrict__ aemb,
            const float* __restrict__ gemb)
{
    constexpr int F4 = 1 << LG;
    long long g = (long long)blockIdx.x * blockDim.x + threadIdx.x;
    int r = (int)(g >> LG);
    if (r >= Nrows) return;
    if (GIDX && r >= *ndev) return;
    int node = GIDX ? lst[r] : r;
    const int c = threadIdx.x & (F4 - 1);
    const int o = off[node], n = cnt[node];

    auto ld = [&](int nb) -> float4 {
        if (XU) {
            if (c < 8)  return ((const float4*)aemb)[((const int2*)x1)[nb].x * 8 + c];
            if (c < 16) return ((const float4*)gemb)[((const int2*)x1)[nb].y * 8 + (c - 8)];
            return ((const float4*)feat)[(size_t)nb * 16 + (c - 16)];
        }
        return ((const float4*)feat)[(size_t)nb * F4 + c];
    };

    float4 acc = make_float4(0.f, 0.f, 0.f, 0.f);
    int i = 0;
    for (; i + 4 <= n; i += 4) {
        int nb0 = csr[o + i],     nb1 = csr[o + i + 1];
        int nb2 = csr[o + i + 2], nb3 = csr[o + i + 3];
        float4 a = ld(nb0);
        float4 b = ld(nb1);
        float4 e = ld(nb2);
        float4 f = ld(nb3);
        acc.x += (a.x + b.x) + (e.x + f.x);
        acc.y += (a.y + b.y) + (e.y + f.y);
        acc.z += (a.z + b.z) + (e.z + f.z);
        acc.w += (a.w + b.w) + (e.w + f.w);
    }
    for (; i < n; i++) {
        float4 a = ld(csr[o + i]);
        acc.x += a.x; acc.y += a.y; acc.z += a.z; acc.w += a.w;
    }
    ((float4*)agg)[(size_t)r * F4 + c] = acc;
}

// ---------------- build tf32 weight image in m16n8k8 B-fragment layout ----------------
__global__ void build_B_kernel(const float* __restrict__ Wl, const float* __restrict__ Wr,
                               int FA, int K, uint32_t* __restrict__ img) {
    int tid = blockIdx.x * blockDim.x + threadIdx.x;
    if (tid >= K * 128) return;
    int k = tid >> 7, n = tid & 127;
    float v = (k < FA) ? Wl[k * 128 + n] : Wr[(k - FA) * 128 + n];
    int ntile = n >> 3;
    int lane  = ((n & 7) << 2) | (k & 3);
    int reg   = (k >> 2) & 1;
    int kstep = k >> 3;
    img[((ntile * (K >> 3) + kstep) * 32 + lane) * 2 + reg] = f2tf32(v);
}

// ================= tf32 mma.sync GEMM core, 64-row M-tile, 2M x 4N warps =========
// GATHER: agg rows are compact (idx), node ids via lst[idx] (cnt/self/out).
template<int FA, int FB, bool DOT, bool GATHER, bool XUF, int MAXB>
__global__ void __launch_bounds__(256, MAXB)
gemm_mma(const float* __restrict__ agg, const int* __restrict__ cnt,
         const float* __restrict__ xr, const uint32_t* __restrict__ Bfrag,
         const float* __restrict__ bias, const float* __restrict__ lw,
         float* __restrict__ out, int Nrows, const int* __restrict__ lst,
         const int* __restrict__ ndev,
         const int* __restrict__ x1, const float* __restrict__ aemb,
         const float* __restrict__ gemb)
{
    constexpr int K   = FA + FB;
    constexpr int KS  = K / 8;
    constexpr int LDA = K + 4;
    constexpr int J   = K / 16;

    const int tile0 = blockIdx.x * 64;
    int nr = Nrows;
    if (GATHER && ndev) nr = *ndev;
    if (tile0 >= nr) return;

    extern __shared__ uint32_t sA[];
    float* part = (float*)(sA + 64 * LDA);
    const int tid  = threadIdx.x;
    const int wid  = tid >> 5;
    const int lane = tid & 31;

    {
        const int row = tid >> 2;
        const int q   = tid & 3;
        int idx = tile0 + row; if (idx >= nr) idx = nr - 1;
        int grow = GATHER ? lst[idx] : idx;
        int arow = GATHER ? idx : grow;   // agg rows compact in GATHER mode
        int c = cnt[grow];
        const float inv = 1.f / (float)(c > 1 ? c : 1);
        const float4* pa = (const float4*)(agg + (size_t)arow * FA);
        const float4* px = (const float4*)(xr  + (size_t)grow * FB);
        int ax = 0, gx = 0;
        if (XUF) { int2 xx = ((const int2*)x1)[grow]; ax = xx.x; gx = xx.y; }
#pragma unroll
        for (int j = 0; j < J; j++) {
            int k4 = q * J + j;
            int kf = k4 * 4;
            float4 v; float sc;
            if (kf < FA) { v = pa[k4]; sc = inv; }
            else if (XUF) {
                int cc = k4 - FA / 4;
                if (cc < 8)       v = ((const float4*)aemb)[ax * 8 + cc];
                else if (cc < 16) v = ((const float4*)gemb)[gx * 8 + (cc - 8)];
                else              v = ((const float4*)xr)[(size_t)grow * 16 + (cc - 16)];
                sc = 1.f;
            } else { v = px[k4 - FA / 4]; sc = 1.f; }
            uint4 t;
            t.x = f2tf32(v.x * sc); t.y = f2tf32(v.y * sc);
            t.z = f2tf32(v.z * sc); t.w = f2tf32(v.w * sc);
            *(uint4*)(sA + row * LDA + kf) = t;
        }
        if (DOT && tid < 64) part[tid] = 0.f;
    }
    __syncthreads();

    const int wm = wid & 1;
    const int wn = wid >> 1;
    const int lr = lane >> 2;
    const int lc = lane & 3;

    float acc[2][4][4];
#pragma unroll
    for (int t = 0; t < 2; t++)
#pragma unroll
        for (int nt = 0; nt < 4; nt++)
#pragma unroll
            for (int q = 0; q < 4; q++) acc[t][nt][q] = 0.f;

    const uint32_t* Ab = sA + (wm * 32 + lr) * LDA + lc;
    const uint2* Bp = (const uint2*)Bfrag + (size_t)(wn * 4) * KS * 32 + lane;

    uint2 bc[4], bn[4];
#pragma unroll
    for (int nt = 0; nt < 4; nt++) bc[nt] = Bp[nt * KS * 32];

#pragma unroll
    for (int ks = 0; ks < KS; ks++) {
        if (ks + 1 < KS) {
#pragma unroll
            for (int nt = 0; nt < 4; nt++) bn[nt] = Bp[nt * KS * 32 + (ks + 1) * 32];
        }
        uint32_t a[2][4];
#pragma unroll
        for (int t = 0; t < 2; t++) {
            const uint32_t* p = Ab + t * 16 * LDA + ks * 8;
            a[t][0] = p[0];
            a[t][1] = p[8 * LDA];
            a[t][2] = p[4];
            a[t][3] = p[8 * LDA + 4];
        }
#pragma unroll
        for (int t = 0; t < 2; t++)
#pragma unroll
            for (int nt = 0; nt < 4; nt++) {
                asm volatile(
                    "mma.sync.aligned.m16n8k8.row.col.f32.tf32.tf32.f32 "
                    "{%0,%1,%2,%3}, {%4,%5,%6,%7}, {%8,%9}, {%0,%1,%2,%3};"
                    : "+f"(acc[t][nt][0]), "+f"(acc[t][nt][1]),
                      "+f"(acc[t][nt][2]), "+f"(acc[t][nt][3])
                    : "r"(a[t][0]), "r"(a[t][1]), "r"(a[t][2]), "r"(a[t][3]),
                      "r"(bc[nt].x), "r"(bc[nt].y));
            }
#pragma unroll
        for (int nt = 0; nt < 4; nt++) bc[nt] = bn[nt];
    }

    if (!DOT) {
#pragma unroll
        for (int nt = 0; nt < 4; nt++) {
            const int col = wn * 32 + nt * 8 + lc * 2;
            const float2 bv = *(const float2*)(bias + col);
#pragma unroll
            for (int t = 0; t < 2; t++) {
                int r0 = tile0 + wm * 32 + t * 16 + lr;
                if (r0 < nr) {
                    float2 o;
                    o.x = fmaxf(acc[t][nt][0] + bv.x, 0.f);
                    o.y = fmaxf(acc[t][nt][1] + bv.y, 0.f);
                    *(float2*)(out + (size_t)r0 * 128 + col) = o;
                }
                int r1 = r0 + 8;
                if (r1 < nr) {
                    float2 o;
                    o.x = fmaxf(acc[t][nt][2] + bv.x, 0.f);
                    o.y = fmaxf(acc[t][nt][3] + bv.y, 0.f);
                    *(float2*)(out + (size_t)r1 * 128 + col) = o;
                }
            }
        }
    } else {
        float p[2][2] = {{0.f, 0.f}, {0.f, 0.f}};
#pragma unroll
        for (int nt = 0; nt < 4; nt++) {
            const int col = wn * 32 + nt * 8 + lc * 2;
            const float2 bv = *(const float2*)(bias + col);
            const float2 wv = *(const float2*)(lw + col);
#pragma unroll
            for (int t = 0; t < 2; t++) {
                p[t][0] += fmaxf(acc[t][nt][0] + bv.x, 0.f) * wv.x
                         + fmaxf(acc[t][nt][1] + bv.y, 0.f) * wv.y;
                p[t][1] += fmaxf(acc[t][nt][2] + bv.x, 0.f) * wv.x
                         + fmaxf(acc[t][nt][3] + bv.y, 0.f) * wv.y;
            }
        }
#pragma unroll
        for (int t = 0; t < 2; t++)
#pragma unroll
            for (int h = 0; h < 2; h++) {
                p[t][h] += __shfl_xor_sync(0xffffffffu, p[t][h], 1);
                p[t][h] += __shfl_xor_sync(0xffffffffu, p[t][h], 2);
            }
        if (lc == 0) {
#pragma unroll
            for (int t = 0; t < 2; t++) {
                atomicAdd(&part[wm * 32 + t * 16 + lr],     p[t][0]);
                atomicAdd(&part[wm * 32 + t * 16 + lr + 8], p[t][1]);
            }
        }
        __syncthreads();
        if (tid < 64) {
            int idx = tile0 + tid;
            if (idx < nr) out[GATHER ? lst[idx] : idx] = part[tid];
        }
    }
}

// ---------------- head: gather both dots, sigmoid ----------------
__global__ void final_kernel(const int* __restrict__ mu, const int* __restrict__ ms,
                             const float* __restrict__ dotU,
                             const float* __restrict__ dotS,
                             const float* __restrict__ lb,
                             float* __restrict__ out) {
    int m = blockIdx.x * blockDim.x + threadIdx.x;
    if (m >= NMx) return;
    float s = dotU[mu[m]] + dotS[ms[m]] + lb[0];
    out[m] = 1.f / (1.f + expf(-s));
}

// ---------------- launcher ----------------
extern "C" void kernel_launch(void* const* d_in, const int* in_sizes, int n_in,
                              void* d_out, int out_size) {
    (void)in_sizes; (void)n_in; (void)out_size;
    const float* x_user_feat   = (const float*)d_in[0];
    const float* x_seller_feat = (const float*)d_in[1];
    const int*   x1            = (const int*)  d_in[2];
    const int*   src_user      = (const int*)  d_in[3];
    const int*   dst_seller    = (const int*)  d_in[4];
    const int*   src_seller    = (const int*)  d_in[5];
    const int*   dst_user      = (const int*)  d_in[6];
    const int*   mask_user     = (const int*)  d_in[7];
    const int*   mask_seller   = (const int*)  d_in[8];
    const float* age_emb       = (const float*)d_in[9];
    const float* gen_emb       = (const float*)d_in[10];
    const float* W1ul = (const float*)d_in[11];
    const float* W1ur = (const float*)d_in[12];
    const float* b1u  = (const float*)d_in[13];
    const float* W1sl = (const float*)d_in[14];
    const float* W1sr = (const float*)d_in[15];
    const float* b1s  = (const float*)d_in[16];
    const float* W2ul = (const float*)d_in[17];
    const float* W2ur = (const float*)d_in[18];
    const float* b2u  = (const float*)d_in[19];
    const float* W2sl = (const float*)d_in[20];
    const float* W2sr = (const float*)d_in[21];
    const float* b2s  = (const float*)d_in[22];
    const float* lin_w = (const float*)d_in[23];
    const float* lin_b = (const float*)d_in[24];
    float* out = (float*)d_out;

    float *aggU, *aggS, *aggU2, *aggS2, *u1, *s1, *dotU, *dotS;
    int *cntU, *cntS, *offU, *offS, *curU, *curS, *csrU, *csrS, *alloc4;
    int *flagU, *flagS, *lstU, *lstS;
    uint32_t* Bimg;
    cudaGetSymbolAddress((void**)&aggU,  g_aggU);
    cudaGetSymbolAddress((void**)&aggS,  g_aggS);
    cudaGetSymbolAddress((void**)&aggU2, g_aggU2);
    cudaGetSymbolAddress((void**)&aggS2, g_aggS2);
    cudaGetSymbolAddress((void**)&u1,    g_u1);
    cudaGetSymbolAddress((void**)&s1,    g_s1);
    cudaGetSymbolAddress((void**)&dotU,  g_dotU);
    cudaGetSymbolAddress((void**)&dotS,  g_dotS);
    cudaGetSymbolAddress((void**)&cntU,  g_cntU);
    cudaGetSymbolAddress((void**)&cntS,  g_cntS);
    cudaGetSymbolAddress((void**)&offU,  g_offU);
    cudaGetSymbolAddress((void**)&offS,  g_offS);
    cudaGetSymbolAddress((void**)&curU,  g_curU);
    cudaGetSymbolAddress((void**)&curS,  g_curS);
    cudaGetSymbolAddress((void**)&csrU,  g_csrU);
    cudaGetSymbolAddress((void**)&csrS,  g_csrS);
    cudaGetSymbolAddress((void**)&lstU,  g_lstU);
    cudaGetSymbolAddress((void**)&lstS,  g_lstS);
    cudaGetSymbolAddress((void**)&alloc4, g_alloc);
    cudaGetSymbolAddress((void**)&flagU, g_flagU);
    cudaGetSymbolAddress((void**)&flagS, g_flagS);
    cudaGetSymbolAddress((void**)&Bimg,  g_Bimg);

    const int SM192 = 64 * (192 + 4) * 4;          // 50176
    const int SM256 = 64 * (256 + 4) * 4 + 256;    // 66816
    cudaFuncSetAttribute((const void*)gemm_mma<64,128,false,false,true,3>,
                         cudaFuncAttributeMaxDynamicSharedMemorySize, SM192);
    cudaFuncSetAttribute((const void*)gemm_mma<128,64,false,false,false,3>,
                         cudaFuncAttributeMaxDynamicSharedMemorySize, SM192);
    cudaFuncSetAttribute((const void*)gemm_mma<128,128,true,true,false,2>,
                         cudaFuncAttributeMaxDynamicSharedMemorySize, SM256);

    static cudaStream_t s2 = nullptr;
    static cudaEvent_t evF, evPrep, evCSRS, evCSRU, evU1, evS1, evG2U;
    if (!s2) {
        cudaStreamCreateWithFlags(&s2, cudaStreamNonBlocking);
        cudaEventCreateWithFlags(&evF,    cudaEventDisableTiming);
        cudaEventCreateWithFlags(&evPrep, cudaEventDisableTiming);
        cudaEventCreateWithFlags(&evCSRS, cudaEventDisableTiming);
        cudaEventCreateWithFlags(&evCSRU, cudaEventDisableTiming);
        cudaEventCreateWithFlags(&evU1,   cudaEventDisableTiming);
        cudaEventCreateWithFlags(&evS1,   cudaEventDisableTiming);
        cudaEventCreateWithFlags(&evG2U,  cudaEventDisableTiming);
    }
    cudaStream_t s0 = 0;
    const int T = 256;

    // ---- fork ----
    cudaEventRecord(evF, s0);
    cudaStreamWaitEvent(s2, evF, 0);

    // ---- s0: shared prep (zeros, flags + compact lists) ----
    prep_zero<<<(NUx + T - 1) / T, T, 0, s0>>>(cntU, cntS, flagU, flagS, alloc4);
    flag_compact<<<(NMx + T - 1) / T, T, 0, s0>>>(mask_user, mask_seller,
                                                  flagU, flagS, lstU, lstS, alloc4);
    cudaEventRecord(evPrep, s0);

    // ---- s2: B images + seller-side CSR + seller L1 chain ----
    build_B_kernel<<<(192*128 + T - 1) / T, T, 0, s2>>>(W1sl, W1sr, 128, 192, Bimg + 1*32768);
    build_B_kernel<<<(256*128 + T - 1) / T, T, 0, s2>>>(W2ul, W2ur, 128, 256, Bimg + 2*32768);
    build_B_kernel<<<(256*128 + T - 1) / T, T, 0, s2>>>(W2sl, W2sr, 128, 256, Bimg + 3*32768);
    cudaStreamWaitEvent(s2, evPrep, 0);
    count_one<<<(NEx + T - 1) / T, T, 0, s2>>>(dst_seller, cntS);
    alloc_kernel<<<(NSx + 255) / 256, 256, 0, s2>>>(cntS, offS, curS, NSx, alloc4, 1);
    fill_one<<<(NEx + T - 1) / T, T, 0, s2>>>(src_user, dst_seller, curS, csrS);
    cudaEventRecord(evCSRS, s2);
    gather_rows<5,false,true><<<(NSx * 32 + T - 1) / T, T, 0, s2>>>(
        x_user_feat, csrS, offS, cntS, aggS, NSx, nullptr, nullptr, x1, age_emb, gen_emb);
    gemm_mma<128,64,false,false,false,3><<<(NSx + 63) / 64, 256, SM192, s2>>>(
        aggS, cntS, x_seller_feat, Bimg + 1*32768, b1s, nullptr, s1, NSx,
        nullptr, nullptr, nullptr, nullptr, nullptr);
    cudaEventRecord(evS1, s2);

    // ---- s0: user-side CSR + user L1 chain + L2 seller branch ----
    build_B_kernel<<<(192*128 + T - 1) / T, T, 0, s0>>>(W1ul, W1ur, 64, 192, Bimg + 0*32768);
    count_one<<<(NEx + T - 1) / T, T, 0, s0>>>(dst_user, cntU);
    alloc_kernel<<<(NUx + 255) / 256, 256, 0, s0>>>(cntU, offU, curU, NUx, alloc4, 0);
    fill_one<<<(NEx + T - 1) / T, T, 0, s0>>>(src_seller, dst_user, curU, csrU);
    cudaEventRecord(evCSRU, s0);
    gather_rows<4,false,false><<<(NUx * 16 + T - 1) / T, T, 0, s0>>>(
        x_seller_feat, csrU, offU, cntU, aggU, NUx, nullptr, nullptr, nullptr, nullptr, nullptr);
    gemm_mma<64,128,false,false,true,3><<<(NUx + 63) / 64, 256, SM192, s0>>>(
        aggU, cntU, x_user_feat, Bimg + 0*32768, b1u, nullptr, u1, NUx,
        nullptr, nullptr, x1, age_emb, gen_emb);
    cudaEventRecord(evU1, s0);
    cudaStreamWaitEvent(s0, evCSRS, 0);
    // compact gather of u1 into aggS2 rows (list order, ~43.2k rows)
    gather_rows<5,true,false><<<(NSx * 32 + T - 1) / T, T, 0, s0>>>(
        u1, csrS, offS, cntS, aggS2, NSx, lstS, alloc4 + 3, nullptr, nullptr, nullptr);
    cudaStreamWaitEvent(s0, evS1, 0);
    gemm_mma<128,128,true,true,false,2><<<(NSx + 63) / 64, 256, SM256, s0>>>(
        aggS2, cntS, s1, Bimg + 3*32768, b2s, lin_w + 128, dotS, NSx,
        lstS, alloc4 + 3, nullptr, nullptr, nullptr);

    // ---- s2: L2 user branch over compact flagged-user list (~78.7k rows) ----
    cudaStreamWaitEvent(s2, evCSRU, 0);
    cudaStreamWaitEvent(s2, evPrep, 0);
    gather_rows<5,true,false><<<(NMx * 32 + T - 1) / T, T, 0, s2>>>(
        s1, csrU, offU, cntU, aggU2, NUx, lstU, alloc4 + 2, nullptr, nullptr, nullptr);
    cudaStreamWaitEvent(s2, evU1, 0);
    gemm_mma<128,128,true,true,false,2><<<(NMx + 63) / 64, 256, SM256, s2>>>(
        aggU2, cntU, u1, Bimg + 2*32768, b2u, lin_w, dotU, NMx,
        lstU, alloc4 + 2, nullptr, nullptr, nullptr);
    cudaEventRecord(evG2U, s2);

    // ---- join + head ----
    cudaStreamWaitEvent(s0, evG2U, 0);
    final_kernel<<<(NMx + T - 1) / T, T, 0, s0>>>(mask_user, mask_seller, dotU, dotS, lin_b, out);
}